// round 14
// baseline (speedup 1.0000x reference)
#include <cuda_runtime.h>

#define NSAMP 8192
#define NOPT  16
#define DIM   768
#define CHUNK_F 64                       // floats per row per chunk
#define NCHUNK (DIM / CHUNK_F)           // 12
#define STAGES 2
#define STAGE_FLOATS (NOPT * CHUNK_F)    // 1024 floats = 4KB per stage
#define NPAIR 136                        // 16*17/2 upper-triangular incl. diagonal
#define HPAIR 68
#define MARGIN 0.3f
#define NEG_INF -1e9f

// Deterministic per-sample scratch (no device-side allocation allowed).
__device__ float g_loss[NSAMP];
__device__ float g_cnt[NSAMP];
__device__ unsigned g_ticket;            // zero-init; reset by finishing block

__device__ __forceinline__ constexpr int triu_idx(int n, int m) {
    // n <= m required. Pairs of row n start at 16n - n(n-1)/2.
    return n * 16 - (n * (n - 1)) / 2 + (m - n);
}

// One warp per sample. 2-stage cp.async pipeline into a per-warp smem ring;
// lane l consumes float2 column l of each 16x64-float tile and accumulates
// all 136 pair partial dot products in registers.
__global__ __launch_bounds__(128, 2)
void gram_kernel(const float* __restrict__ emb, const int* __restrict__ labels,
                 float* __restrict__ out)
{
    __shared__ float ring[4][STAGES * STAGE_FLOATS];   // 32 KB static
    const int warp = threadIdx.x >> 5;
    const int lane = threadIdx.x & 31;
    const int sample = blockIdx.x * 4 + warp;

    float* wbuf = ring[warp];
    const float* gp = emb + (size_t)sample * (NOPT * DIM);

    // pos/neg bitmasks from int32 labels (lanes 0..15 read one each).
    int lab = (lane < NOPT) ? labels[(size_t)sample * NOPT + lane] : -1;
    const unsigned pos_mask = __ballot_sync(0xffffffffu, (lane < NOPT) && (lab == 1));
    const unsigned neg_mask = __ballot_sync(0xffffffffu, (lane < NOPT) && (lab == 0));

    // cp.async addressing: each lane copies 16B; 2 rows per instruction,
    // 8 instructions cover the 16x64-float (4KB) stage tile.
    const int row0 = lane >> 4;          // 0 or 1
    const int colf = (lane & 15) * 4;    // float index 0..60, 16B-aligned

    auto issue_stage = [&](int c, int s) {
        const float* src0 = gp + c * CHUNK_F + colf;
        unsigned dst0 = (unsigned)__cvta_generic_to_shared(
            wbuf + s * STAGE_FLOATS + colf);
#pragma unroll
        for (int j = 0; j < 8; ++j) {
            int row = j * 2 + row0;
            asm volatile("cp.async.cg.shared.global [%0], [%1], 16;"
                         :: "r"(dst0 + row * (CHUNK_F * 4)),
                            "l"(src0 + row * DIM) : "memory");
        }
        asm volatile("cp.async.commit_group;" ::: "memory");
    };

    issue_stage(0, 0);
    issue_stage(1, 1);

    float acc[NPAIR];
#pragma unroll
    for (int i = 0; i < NPAIR; ++i) acc[i] = 0.0f;

#pragma unroll 1
    for (int c = 0; c < NCHUNK; ++c) {
        // Drain until group c has landed. While a younger prefetch is still
        // pending, allow exactly 1 group in flight; on the FINAL chunk there
        // is no younger group, so we must drain to 0 (wait_group 1 would
        // return without waiting for it -- this was the R13 race).
        if (c + 1 < NCHUNK)
            asm volatile("cp.async.wait_group 1;" ::: "memory");
        else
            asm volatile("cp.async.wait_group 0;" ::: "memory");
        __syncwarp();

        const float2* xs = (const float2*)(wbuf + (c % STAGES) * STAGE_FLOATS);
        float2 x[NOPT];
#pragma unroll
        for (int n = 0; n < NOPT; ++n)
            x[n] = xs[n * 32 + lane];    // LDS.64, conflict-free

        __syncwarp();                    // all lanes done reading slot c%2
        if (c + 2 < NCHUNK)
            issue_stage(c + 2, c % STAGES);   // (c+2)%2 == c%2

#pragma unroll
        for (int n = 0; n < NOPT; ++n) {
#pragma unroll
            for (int m = n; m < NOPT; ++m) {
                float v = acc[triu_idx(n, m)];
                v = fmaf(x[n].x, x[m].x, v);
                v = fmaf(x[n].y, x[m].y, v);
                acc[triu_idx(n, m)] = v;
            }
        }
    }

    // Cross-lane reduction, two pairs per 5-level butterfly:
    // lanes 0-15 carry pair i, lanes 16-31 carry pair i+68.
    __shared__ float ssum[4][NPAIR];
    float* s = ssum[warp];
#pragma unroll
    for (int i = 0; i < HPAIR; ++i) {
        float a = acc[i], b = acc[i + HPAIR];
        float keep = (lane < 16) ? a : b;
        float send = (lane < 16) ? b : a;
        float w = keep + __shfl_xor_sync(0xffffffffu, send, 16);
        w += __shfl_xor_sync(0xffffffffu, w, 8);
        w += __shfl_xor_sync(0xffffffffu, w, 4);
        w += __shfl_xor_sync(0xffffffffu, w, 2);
        w += __shfl_xor_sync(0xffffffffu, w, 1);
        if (lane == 0)  s[i] = w;
        if (lane == 16) s[i + HPAIR] = w;
    }
    __syncwarp();

    // Inverse norms: lane m computes its own, then broadcast-gather all 16.
    float inv_own = 0.0f;
    if (lane < NOPT) {
        float nrm = sqrtf(s[triu_idx(lane, lane)]);
        inv_own = 1.0f / fmaxf(nrm, 1e-12f);
    }
    float inv[NOPT];
#pragma unroll
    for (int m = 0; m < NOPT; ++m)
        inv[m] = __shfl_sync(0xffffffffu, inv_own, m);

    const bool valid = (pos_mask != 0u) && (neg_mask != 0u);

    // Lane n handles row n: max cosine sim against negative columns.
    float triplet = 0.0f;
    if (lane < NOPT && valid && ((pos_mask >> lane) & 1u)) {
        float mx = NEG_INF;
#pragma unroll
        for (int m = 0; m < NOPT; ++m) {
            if ((neg_mask >> m) & 1u) {
                int a = lane < m ? lane : m;
                int b = lane < m ? m : lane;
                float sim = s[triu_idx(a, b)] * inv[lane] * inv[m];
                mx = fmaxf(mx, sim);
            }
        }
        triplet = fmaxf(mx + MARGIN, 0.0f);
    }

    // Warp-sum triplet contributions.
    float tsum = triplet;
    tsum += __shfl_xor_sync(0xffffffffu, tsum, 16);
    tsum += __shfl_xor_sync(0xffffffffu, tsum, 8);
    tsum += __shfl_xor_sync(0xffffffffu, tsum, 4);
    tsum += __shfl_xor_sync(0xffffffffu, tsum, 2);
    tsum += __shfl_xor_sync(0xffffffffu, tsum, 1);

    if (lane == 0) {
        g_loss[sample] = tsum;
        g_cnt[sample]  = valid ? (float)__popc(pos_mask) : 0.0f;
    }

    // ── Fused deterministic final reduction (last-block pattern) ──
    // Fixed tree over g_loss/g_cnt: result independent of which block runs it.
    __syncthreads();
    __shared__ unsigned s_ticket;
    if (threadIdx.x == 0) {
        __threadfence();                   // publish this block's results
        s_ticket = atomicAdd(&g_ticket, 1u);
    }
    __syncthreads();
    if (s_ticket == gridDim.x - 1) {
        __threadfence();                   // acquire all blocks' results
        __shared__ float sl[128], sc[128];
        const int t = threadIdx.x;
        float ls = 0.0f, cs = 0.0f;
        for (int i = t; i < NSAMP; i += 128) {
            ls += g_loss[i];
            cs += g_cnt[i];
        }
        sl[t] = ls; sc[t] = cs;
        __syncthreads();
#pragma unroll
        for (int stride = 64; stride > 0; stride >>= 1) {
            if (t < stride) { sl[t] += sl[t + stride]; sc[t] += sc[t + stride]; }
            __syncthreads();
        }
        if (t == 0) {
            out[0] = sl[0] / fmaxf(sc[0], 1.0f);
            g_ticket = 0;                  // reset for next graph replay
        }
    }
}

extern "C" void kernel_launch(void* const* d_in, const int* in_sizes, int n_in,
                              void* d_out, int out_size)
{
    const float* emb = (const float*)d_in[0];    // [8192, 16, 768] float32
    const int* labels = (const int*)d_in[1];     // [8192, 16] int32 (verified R5/R9)
    float* out = (float*)d_out;                  // scalar float32

    (void)in_sizes; (void)n_in; (void)out_size;

    gram_kernel<<<NSAMP / 4, 128>>>(emb, labels, out);
}

// round 15
// speedup vs baseline: 1.5027x; 1.5027x over previous
#include <cuda_runtime.h>

#define NSAMP 8192
#define NOPT  16
#define DIM   768
#define NV2   (DIM / 2)        // 384 float2 per row
#define CHUNKS (NV2 / 32)      // 12 chunks of 32 float2 per lane
#define NPAIR 136              // 16*17/2 upper-triangular incl. diagonal
#define HACC  68               // accumulators per warp (pair-parity split)
#define QACC  34               // HACC/2 (merged butterfly trees)
#define MARGIN 0.3f
#define NEG_INF -1e9f

// Deterministic per-sample scratch (no device-side allocation allowed).
__device__ float g_loss[NSAMP];
__device__ float g_cnt[NSAMP];
__device__ unsigned g_ticket;            // zero-init; reset by finishing block

__device__ __forceinline__ constexpr int triu_idx(int n, int m) {
    return n * 16 - (n * (n - 1)) / 2 + (m - n);
}

// Mainloop for one warp-half. HALF selects even/odd pairs of the flattened
// upper-triangular enumeration; with full unroll every acc index and row
// index is a compile-time constant -> exactly 68 live accumulators.
template <int HALF>
__device__ __forceinline__ void mainloop(const float2* __restrict__ p2,
                                         int lane, float* __restrict__ acc)
{
#pragma unroll 1
    for (int c = 0; c < CHUNKS; ++c) {
        float2 x[NOPT];
        const float2* p = p2 + lane + c * 32;
#pragma unroll
        for (int n = 0; n < NOPT; ++n)
            x[n] = p[n * NV2];           // LDG.64; 2nd warp of the pair hits L1
        int k = 0;
#pragma unroll
        for (int n = 0; n < NOPT; ++n) {
#pragma unroll
            for (int m = n; m < NOPT; ++m) {
                if ((k & 1) == HALF) {
                    const int a = k >> 1;
                    float v = acc[a];
                    v = fmaf(x[n].x, x[m].x, v);
                    v = fmaf(x[n].y, x[m].y, v);
                    acc[a] = v;
                }
                ++k;
            }
        }
    }
}

// Two warps per sample (pair-parity split), 2 samples per 128-thread block.
__global__ __launch_bounds__(128, 4)
void gram_kernel(const float* __restrict__ emb, const int* __restrict__ labels,
                 float* __restrict__ out)
{
    const int warp = threadIdx.x >> 5;
    const int lane = threadIdx.x & 31;
    const int half = warp & 1;           // which pair-parity this warp owns
    const int sloc = warp >> 1;          // sample index within block (0/1)
    const int sample = blockIdx.x * 2 + sloc;

    const float2* p2 = (const float2*)(emb + (size_t)sample * (NOPT * DIM));

    float acc[HACC];
#pragma unroll
    for (int i = 0; i < HACC; ++i) acc[i] = 0.0f;

    if (half == 0) mainloop<0>(p2, lane, acc);
    else           mainloop<1>(p2, lane, acc);

    // Cross-lane reduction: merge two accs per 5-level butterfly.
    // lanes 0-15 carry acc[i], lanes 16-31 carry acc[i+34].
    __shared__ float ssum[2][NPAIR];
    float* s = ssum[sloc];
#pragma unroll
    for (int i = 0; i < QACC; ++i) {
        float a = acc[i], b = acc[i + QACC];
        float keep = (lane < 16) ? a : b;
        float send = (lane < 16) ? b : a;
        float w = keep + __shfl_xor_sync(0xffffffffu, send, 16);
        w += __shfl_xor_sync(0xffffffffu, w, 8);
        w += __shfl_xor_sync(0xffffffffu, w, 4);
        w += __shfl_xor_sync(0xffffffffu, w, 2);
        w += __shfl_xor_sync(0xffffffffu, w, 1);
        if (lane == 0)  s[2 * i + half] = w;                // pair k = 2i+half
        if (lane == 16) s[2 * (i + QACC) + half] = w;       // pair k = 2(i+34)+half
    }
    __syncthreads();                     // both halves' 68 sums visible

    // Epilogue on the even warp of each sample.
    if (half == 0) {
        // pos/neg bitmasks from int32 labels (lanes 0..15 read one each).
        int lab = (lane < NOPT) ? labels[(size_t)sample * NOPT + lane] : -1;
        const unsigned pos_mask = __ballot_sync(0xffffffffu, (lane < NOPT) && (lab == 1));
        const unsigned neg_mask = __ballot_sync(0xffffffffu, (lane < NOPT) && (lab == 0));

        float inv_own = 0.0f;
        if (lane < NOPT) {
            float nrm = sqrtf(s[triu_idx(lane, lane)]);
            inv_own = 1.0f / fmaxf(nrm, 1e-12f);
        }
        float inv[NOPT];
#pragma unroll
        for (int m = 0; m < NOPT; ++m)
            inv[m] = __shfl_sync(0xffffffffu, inv_own, m);

        const bool valid = (pos_mask != 0u) && (neg_mask != 0u);

        float triplet = 0.0f;
        if (lane < NOPT && valid && ((pos_mask >> lane) & 1u)) {
            float mx = NEG_INF;
#pragma unroll
            for (int m = 0; m < NOPT; ++m) {
                if ((neg_mask >> m) & 1u) {
                    int a = lane < m ? lane : m;
                    int b = lane < m ? m : lane;
                    float sim = s[triu_idx(a, b)] * inv[lane] * inv[m];
                    mx = fmaxf(mx, sim);
                }
            }
            triplet = fmaxf(mx + MARGIN, 0.0f);
        }

        float tsum = triplet;
        tsum += __shfl_xor_sync(0xffffffffu, tsum, 16);
        tsum += __shfl_xor_sync(0xffffffffu, tsum, 8);
        tsum += __shfl_xor_sync(0xffffffffu, tsum, 4);
        tsum += __shfl_xor_sync(0xffffffffu, tsum, 2);
        tsum += __shfl_xor_sync(0xffffffffu, tsum, 1);

        if (lane == 0) {
            g_loss[sample] = tsum;
            g_cnt[sample]  = valid ? (float)__popc(pos_mask) : 0.0f;
        }
    }

    // ── Fused deterministic final reduction (last-block pattern) ──
    __syncthreads();
    __shared__ unsigned s_ticket;
    if (threadIdx.x == 0) {
        __threadfence();                   // publish this block's results
        s_ticket = atomicAdd(&g_ticket, 1u);
    }
    __syncthreads();
    if (s_ticket == gridDim.x - 1) {
        __threadfence();                   // acquire all blocks' results
        __shared__ float sl[128], sc[128];
        const int t = threadIdx.x;
        float ls = 0.0f, cs = 0.0f;
        for (int i = t; i < NSAMP; i += 128) {
            ls += g_loss[i];
            cs += g_cnt[i];
        }
        sl[t] = ls; sc[t] = cs;
        __syncthreads();
#pragma unroll
        for (int stride = 64; stride > 0; stride >>= 1) {
            if (t < stride) { sl[t] += sl[t + stride]; sc[t] += sc[t + stride]; }
            __syncthreads();
        }
        if (t == 0) {
            out[0] = sl[0] / fmaxf(sc[0], 1.0f);
            g_ticket = 0;                  // reset for next graph replay
        }
    }
}

extern "C" void kernel_launch(void* const* d_in, const int* in_sizes, int n_in,
                              void* d_out, int out_size)
{
    const float* emb = (const float*)d_in[0];    // [8192, 16, 768] float32
    const int* labels = (const int*)d_in[1];     // [8192, 16] int32 (verified R5/R9)
    float* out = (float*)d_out;                  // scalar float32

    (void)in_sizes; (void)n_in; (void)out_size;

    gram_kernel<<<NSAMP / 2, 128>>>(emb, labels, out);
}

// round 16
// speedup vs baseline: 1.5398x; 1.0247x over previous
#include <cuda_runtime.h>

#define NSAMP 8192
#define NOPT  16
#define DIM   768
#define NV2   (DIM / 2)        // 384 float2 per row
#define CHUNKS (NV2 / 32)      // 12 chunks of 32 float2 per lane
#define NPAIR 136              // 16*17/2 upper-triangular incl. diagonal
#define HACC  68               // accumulators per warp (pair-parity split)
#define QACC  34               // HACC/2 (merged butterfly trees)
#define MARGIN 0.3f
#define NEG_INF -1e9f

// Deterministic per-sample scratch (no device-side allocation allowed).
__device__ float g_loss[NSAMP];
__device__ float g_cnt[NSAMP];
__device__ unsigned g_ticket;            // zero-init; reset by finishing block

__device__ __forceinline__ constexpr int triu_idx(int n, int m) {
    return n * 16 - (n * (n - 1)) / 2 + (m - n);
}

// Mainloop for one warp-half. HALF selects even/odd pairs of the flattened
// upper-triangular enumeration; with full unroll every acc index and row
// index is a compile-time constant -> exactly 68 live accumulators.
// `phase` rotates the chunk order per warp: breaks the load-stream phase lock
// between the two warps of a sample (and between the block's two samples),
// and converts the partner warp's duplicate reads into L2 hits.
template <int HALF>
__device__ __forceinline__ void mainloop(const float2* __restrict__ p2,
                                         int lane, int phase,
                                         float* __restrict__ acc)
{
#pragma unroll 1
    for (int c = 0; c < CHUNKS; ++c) {
        int cc = c + phase;
        if (cc >= CHUNKS) cc -= CHUNKS;
        float2 x[NOPT];
        const float2* p = p2 + lane + cc * 32;
#pragma unroll
        for (int n = 0; n < NOPT; ++n)
            x[n] = p[n * NV2];           // LDG.64, coalesced
        int k = 0;
#pragma unroll
        for (int n = 0; n < NOPT; ++n) {
#pragma unroll
            for (int m = n; m < NOPT; ++m) {
                if ((k & 1) == HALF) {
                    const int a = k >> 1;
                    float v = acc[a];
                    v = fmaf(x[n].x, x[m].x, v);
                    v = fmaf(x[n].y, x[m].y, v);
                    acc[a] = v;
                }
                ++k;
            }
        }
    }
}

// Two warps per sample (pair-parity split), 2 samples per 128-thread block.
__global__ __launch_bounds__(128, 4)
void gram_kernel(const float* __restrict__ emb, const int* __restrict__ labels,
                 float* __restrict__ out)
{
    const int warp = threadIdx.x >> 5;
    const int lane = threadIdx.x & 31;
    const int half = warp & 1;           // which pair-parity this warp owns
    const int sloc = warp >> 1;          // sample index within block (0/1)
    const int sample = blockIdx.x * 2 + sloc;
    const int phase = warp * 3;          // chunk phases 0,3,6,9 across the block

    const float2* p2 = (const float2*)(emb + (size_t)sample * (NOPT * DIM));

    float acc[HACC];
#pragma unroll
    for (int i = 0; i < HACC; ++i) acc[i] = 0.0f;

    if (half == 0) mainloop<0>(p2, lane, phase, acc);
    else           mainloop<1>(p2, lane, phase, acc);

    // Cross-lane reduction: merge two accs per 5-level butterfly.
    // lanes 0-15 carry acc[i], lanes 16-31 carry acc[i+34].
    __shared__ float ssum[2][NPAIR];
    float* s = ssum[sloc];
#pragma unroll
    for (int i = 0; i < QACC; ++i) {
        float a = acc[i], b = acc[i + QACC];
        float keep = (lane < 16) ? a : b;
        float send = (lane < 16) ? b : a;
        float w = keep + __shfl_xor_sync(0xffffffffu, send, 16);
        w += __shfl_xor_sync(0xffffffffu, w, 8);
        w += __shfl_xor_sync(0xffffffffu, w, 4);
        w += __shfl_xor_sync(0xffffffffu, w, 2);
        w += __shfl_xor_sync(0xffffffffu, w, 1);
        if (lane == 0)  s[2 * i + half] = w;                // pair k = 2i+half
        if (lane == 16) s[2 * (i + QACC) + half] = w;       // pair k = 2(i+34)+half
    }
    __syncthreads();                     // both halves' 68 sums visible

    // Epilogue on the even warp of each sample.
    if (half == 0) {
        // pos/neg bitmasks from int32 labels (lanes 0..15 read one each).
        int lab = (lane < NOPT) ? labels[(size_t)sample * NOPT + lane] : -1;
        const unsigned pos_mask = __ballot_sync(0xffffffffu, (lane < NOPT) && (lab == 1));
        const unsigned neg_mask = __ballot_sync(0xffffffffu, (lane < NOPT) && (lab == 0));

        float inv_own = 0.0f;
        if (lane < NOPT) {
            float nrm = sqrtf(s[triu_idx(lane, lane)]);
            inv_own = 1.0f / fmaxf(nrm, 1e-12f);
        }
        float inv[NOPT];
#pragma unroll
        for (int m = 0; m < NOPT; ++m)
            inv[m] = __shfl_sync(0xffffffffu, inv_own, m);

        const bool valid = (pos_mask != 0u) && (neg_mask != 0u);

        float triplet = 0.0f;
        if (lane < NOPT && valid && ((pos_mask >> lane) & 1u)) {
            float mx = NEG_INF;
#pragma unroll
            for (int m = 0; m < NOPT; ++m) {
                if ((neg_mask >> m) & 1u) {
                    int a = lane < m ? lane : m;
                    int b = lane < m ? m : lane;
                    float sim = s[triu_idx(a, b)] * inv[lane] * inv[m];
                    mx = fmaxf(mx, sim);
                }
            }
            triplet = fmaxf(mx + MARGIN, 0.0f);
        }

        float tsum = triplet;
        tsum += __shfl_xor_sync(0xffffffffu, tsum, 16);
        tsum += __shfl_xor_sync(0xffffffffu, tsum, 8);
        tsum += __shfl_xor_sync(0xffffffffu, tsum, 4);
        tsum += __shfl_xor_sync(0xffffffffu, tsum, 2);
        tsum += __shfl_xor_sync(0xffffffffu, tsum, 1);

        if (lane == 0) {
            g_loss[sample] = tsum;
            g_cnt[sample]  = valid ? (float)__popc(pos_mask) : 0.0f;
        }
    }

    // ── Fused deterministic final reduction (last-block pattern) ──
    __syncthreads();
    __shared__ unsigned s_ticket;
    if (threadIdx.x == 0) {
        __threadfence();                   // publish this block's results
        s_ticket = atomicAdd(&g_ticket, 1u);
    }
    __syncthreads();
    if (s_ticket == gridDim.x - 1) {
        __threadfence();                   // acquire all blocks' results
        __shared__ float sl[128], sc[128];
        const int t = threadIdx.x;
        float ls = 0.0f, cs = 0.0f;
        for (int i = t; i < NSAMP; i += 128) {
            ls += g_loss[i];
            cs += g_cnt[i];
        }
        sl[t] = ls; sc[t] = cs;
        __syncthreads();
#pragma unroll
        for (int stride = 64; stride > 0; stride >>= 1) {
            if (t < stride) { sl[t] += sl[t + stride]; sc[t] += sc[t + stride]; }
            __syncthreads();
        }
        if (t == 0) {
            out[0] = sl[0] / fmaxf(sc[0], 1.0f);
            g_ticket = 0;                  // reset for next graph replay
        }
    }
}

extern "C" void kernel_launch(void* const* d_in, const int* in_sizes, int n_in,
                              void* d_out, int out_size)
{
    const float* emb = (const float*)d_in[0];    // [8192, 16, 768] float32
    const int* labels = (const int*)d_in[1];     // [8192, 16] int32 (verified R5/R9)
    float* out = (float*)d_out;                  // scalar float32

    (void)in_sizes; (void)n_in; (void)out_size;

    gram_kernel<<<NSAMP / 2, 128>>>(emb, labels, out);
}

// round 17
// speedup vs baseline: 1.7595x; 1.1427x over previous
#include <cuda_runtime.h>

#define NSAMP 8192
#define NOPT  16
#define DIM   768
#define CHUNK_F 64                       // floats per row per chunk
#define NCHUNK (DIM / CHUNK_F)           // 12
#define STAGES 4
#define STAGE_FLOATS (NOPT * CHUNK_F)    // 1024 floats = 4KB per stage
#define NPAIR 136
#define HACC  68                         // accumulators per warp (pair-parity split)
#define QACC  34
#define MARGIN 0.3f
#define NEG_INF -1e9f

// Deterministic per-sample scratch (no device-side allocation allowed).
__device__ float g_loss[NSAMP];
__device__ float g_cnt[NSAMP];
__device__ unsigned g_ticket;            // zero-init; reset by finishing block

__device__ __forceinline__ constexpr int triu_idx(int n, int m) {
    return n * 16 - (n * (n - 1)) / 2 + (m - n);
}

// FMA parity half: compile-time HALF keeps all 68 acc indices constant.
template <int HALF>
__device__ __forceinline__ void fma_half(const float2* __restrict__ x,
                                         float* __restrict__ acc)
{
    int k = 0;
#pragma unroll
    for (int n = 0; n < NOPT; ++n) {
#pragma unroll
        for (int m = n; m < NOPT; ++m) {
            if ((k & 1) == HALF) {
                const int a = k >> 1;
                float v = acc[a];
                v = fmaf(x[n].x, x[m].x, v);
                v = fmaf(x[n].y, x[m].y, v);
                acc[a] = v;
            }
            ++k;
        }
    }
}

// Cooperative stage fill: this warp copies its 8 rows (half*8..half*8+7) of
// chunk c into stage slot c%4. 4 LDGSTS per thread = 2KB per warp; the
// partner warp fills the other 8 rows. One commit_group per warp per stage.
__device__ __forceinline__ void issue_stage(const float* __restrict__ gp,
                                            float* __restrict__ sbuf,
                                            int c, int half, int lane)
{
    float* dst_base = sbuf + (c & (STAGES - 1)) * STAGE_FLOATS;
    const int colf = (lane & 15) * 4;          // 16B-aligned float col
    const int r0 = half * 8 + (lane >> 4);     // base row for this lane
#pragma unroll
    for (int j = 0; j < 4; ++j) {
        int row = r0 + j * 2;
        unsigned dst = (unsigned)__cvta_generic_to_shared(
            dst_base + row * CHUNK_F + colf);
        asm volatile("cp.async.cg.shared.global [%0], [%1], 16;"
                     :: "r"(dst), "l"(gp + row * DIM + c * CHUNK_F + colf)
                     : "memory");
    }
    asm volatile("cp.async.commit_group;" ::: "memory");
}

// Two warps per sample (pair-parity split), 2 samples per 128-thread block.
// 4-stage cp.async pipeline into a per-SAMPLE shared ring.
__global__ __launch_bounds__(128, 4)
void gram_kernel(const float* __restrict__ emb, const int* __restrict__ labels,
                 float* __restrict__ out)
{
    __shared__ float ring[2][STAGES * STAGE_FLOATS];   // 32 KB
    __shared__ float ssum[2][NPAIR];

    const int warp = threadIdx.x >> 5;
    const int lane = threadIdx.x & 31;
    const int half = warp & 1;           // pair-parity / row-half owner
    const int sloc = warp >> 1;          // sample index within block (0/1)
    const int sample = blockIdx.x * 2 + sloc;

    const float* gp = emb + (size_t)sample * (NOPT * DIM);
    float* sbuf = ring[sloc];

    // Prologue: 3 stages ahead.
    issue_stage(gp, sbuf, 0, half, lane);
    issue_stage(gp, sbuf, 1, half, lane);
    issue_stage(gp, sbuf, 2, half, lane);

    float acc[HACC];
#pragma unroll
    for (int i = 0; i < HACC; ++i) acc[i] = 0.0f;

#pragma unroll 1
    for (int c = 0; c < NCHUNK; ++c) {
        // Drain own groups until stage c has landed. Younger groups still
        // issued: min(2, NCHUNK-1-c) -> explicit immediate ladder (tail
        // must drain harder; wait_group with too-large N was the R13 race).
        if (c <= NCHUNK - 3)
            asm volatile("cp.async.wait_group 2;" ::: "memory");
        else if (c == NCHUNK - 2)
            asm volatile("cp.async.wait_group 1;" ::: "memory");
        else
            asm volatile("cp.async.wait_group 0;" ::: "memory");
        __syncthreads();                 // partner warp's half also landed;
                                         // also fences last iteration's reads
                                         // before slot (c+3)%4 is overwritten

        const float2* xs = (const float2*)(sbuf + (c & (STAGES - 1)) * STAGE_FLOATS);
        float2 x[NOPT];
#pragma unroll
        for (int n = 0; n < NOPT; ++n)
            x[n] = xs[n * 32 + lane];    // LDS.64, conflict-free

        if (c + 3 < NCHUNK)
            issue_stage(gp, sbuf, c + 3, half, lane);

        if (half == 0) fma_half<0>(x, acc);
        else           fma_half<1>(x, acc);
    }

    // Cross-lane reduction: merge two accs per 5-level butterfly.
    float* s = ssum[sloc];
#pragma unroll
    for (int i = 0; i < QACC; ++i) {
        float a = acc[i], b = acc[i + QACC];
        float keep = (lane < 16) ? a : b;
        float send = (lane < 16) ? b : a;
        float w = keep + __shfl_xor_sync(0xffffffffu, send, 16);
        w += __shfl_xor_sync(0xffffffffu, w, 8);
        w += __shfl_xor_sync(0xffffffffu, w, 4);
        w += __shfl_xor_sync(0xffffffffu, w, 2);
        w += __shfl_xor_sync(0xffffffffu, w, 1);
        if (lane == 0)  s[2 * i + half] = w;             // pair k = 2i+half
        if (lane == 16) s[2 * (i + QACC) + half] = w;    // pair k = 2(i+34)+half
    }
    __syncthreads();                     // both halves' 68 sums visible

    // Epilogue on the even warp of each sample.
    if (half == 0) {
        int lab = (lane < NOPT) ? labels[(size_t)sample * NOPT + lane] : -1;
        const unsigned pos_mask = __ballot_sync(0xffffffffu, (lane < NOPT) && (lab == 1));
        const unsigned neg_mask = __ballot_sync(0xffffffffu, (lane < NOPT) && (lab == 0));

        float inv_own = 0.0f;
        if (lane < NOPT) {
            float nrm = sqrtf(s[triu_idx(lane, lane)]);
            inv_own = 1.0f / fmaxf(nrm, 1e-12f);
        }
        float inv[NOPT];
#pragma unroll
        for (int m = 0; m < NOPT; ++m)
            inv[m] = __shfl_sync(0xffffffffu, inv_own, m);

        const bool valid = (pos_mask != 0u) && (neg_mask != 0u);

        float triplet = 0.0f;
        if (lane < NOPT && valid && ((pos_mask >> lane) & 1u)) {
            float mx = NEG_INF;
#pragma unroll
            for (int m = 0; m < NOPT; ++m) {
                if ((neg_mask >> m) & 1u) {
                    int a = lane < m ? lane : m;
                    int b = lane < m ? m : lane;
                    float sim = s[triu_idx(a, b)] * inv[lane] * inv[m];
                    mx = fmaxf(mx, sim);
                }
            }
            triplet = fmaxf(mx + MARGIN, 0.0f);
        }

        float tsum = triplet;
        tsum += __shfl_xor_sync(0xffffffffu, tsum, 16);
        tsum += __shfl_xor_sync(0xffffffffu, tsum, 8);
        tsum += __shfl_xor_sync(0xffffffffu, tsum, 4);
        tsum += __shfl_xor_sync(0xffffffffu, tsum, 2);
        tsum += __shfl_xor_sync(0xffffffffu, tsum, 1);

        if (lane == 0) {
            g_loss[sample] = tsum;
            g_cnt[sample]  = valid ? (float)__popc(pos_mask) : 0.0f;
        }
    }

    // ── Fused deterministic final reduction (last-block pattern) ──
    __syncthreads();
    __shared__ unsigned s_ticket;
    if (threadIdx.x == 0) {
        __threadfence();                   // publish this block's results
        s_ticket = atomicAdd(&g_ticket, 1u);
    }
    __syncthreads();
    if (s_ticket == gridDim.x - 1) {
        __threadfence();                   // acquire all blocks' results
        __shared__ float sl[128], sc[128];
        const int t = threadIdx.x;
        float ls = 0.0f, cs = 0.0f;
        for (int i = t; i < NSAMP; i += 128) {
            ls += g_loss[i];
            cs += g_cnt[i];
        }
        sl[t] = ls; sc[t] = cs;
        __syncthreads();
#pragma unroll
        for (int stride = 64; stride > 0; stride >>= 1) {
            if (t < stride) { sl[t] += sl[t + stride]; sc[t] += sc[t + stride]; }
            __syncthreads();
        }
        if (t == 0) {
            out[0] = sl[0] / fmaxf(sc[0], 1.0f);
            g_ticket = 0;                  // reset for next graph replay
        }
    }
}

extern "C" void kernel_launch(void* const* d_in, const int* in_sizes, int n_in,
                              void* d_out, int out_size)
{
    const float* emb = (const float*)d_in[0];    // [8192, 16, 768] float32
    const int* labels = (const int*)d_in[1];     // [8192, 16] int32 (verified R5/R9)
    float* out = (float*)d_out;                  // scalar float32

    (void)in_sizes; (void)n_in; (void)out_size;

    gram_kernel<<<NSAMP / 2, 128>>>(emb, labels, out);
}